// round 14
// baseline (speedup 1.0000x reference)
#include <cuda_runtime.h>

#define NSAMP 65536
#define EPSF 1e-8f
#define LOG2E 1.44269504f
#define BLOCK_THREADS 128
#define NBLOCKS 592                    // 4 CTAs/SM x 148 SMs: single resident wave
#define TOTAL_WARPS (NBLOCKS * (BLOCK_THREADS / 32))

// Warp-per-sample, register-resident, single-wave persistent kernel.
// Lane l -> (o = l>>1, i-half h = l&1); butterfly slot order (slot m holds
// logical i = h*8 + (m^perm)) keeps the softmax reduction select-free.
// NEW: all heavy FMA blocks run on packed f32x2 (FFMA2), pairing slots
// (2p, 2p+1); packed votes stay packed through iter-0 sums, einsum and
// b-update. Negation via xor.b64 sign flip (alu pipe). b is kept in the
// log2 domain so softmax exp is a bare ex2.approx.

typedef unsigned long long u64;

__device__ __forceinline__ float fastrcp(float d) {
    float r; asm("rcp.approx.f32 %0, %1;" : "=f"(r) : "f"(d)); return r;
}
__device__ __forceinline__ float ex2f(float x) {
    float r; asm("ex2.approx.f32 %0, %1;" : "=f"(r) : "f"(x)); return r;
}
__device__ __forceinline__ u64 pk2(float lo, float hi) {
    u64 r; asm("mov.b64 %0, {%1, %2};" : "=l"(r) : "f"(lo), "f"(hi)); return r;
}
__device__ __forceinline__ void upk2(u64 v, float& lo, float& hi) {
    asm("mov.b64 {%0, %1}, %2;" : "=f"(lo), "=f"(hi) : "l"(v));
}
__device__ __forceinline__ u64 fma2(u64 a, u64 b, u64 c) {
    u64 d; asm("fma.rn.f32x2 %0, %1, %2, %3;" : "=l"(d) : "l"(a), "l"(b), "l"(c)); return d;
}
__device__ __forceinline__ u64 mul2(u64 a, u64 b) {
    u64 d; asm("mul.rn.f32x2 %0, %1, %2;" : "=l"(d) : "l"(a), "l"(b)); return d;
}
__device__ __forceinline__ u64 add2(u64 a, u64 b) {
    u64 d; asm("add.rn.f32x2 %0, %1, %2;" : "=l"(d) : "l"(a), "l"(b)); return d;
}
__device__ __forceinline__ u64 neg2(u64 a) {   // flip both sign bits (alu pipe)
    u64 d; asm("xor.b64 %0, %1, 0x8000000080000000;" : "=l"(d) : "l"(a)); return d;
}

__global__ void __launch_bounds__(BLOCK_THREADS, 4)
caps_quat_kernel(const float* __restrict__ x,
                 const float* __restrict__ quats,
                 const float* __restrict__ scale,
                 const float* __restrict__ trans,
                 const float* __restrict__ bias,
                 const float* __restrict__ beta,
                 const float* __restrict__ alpha,
                 float* __restrict__ out)
{
    const int lane = threadIdx.x & 31;
    const int warp = blockIdx.x * (BLOCK_THREADS / 32) + (threadIdx.x >> 5);
    const int h    = lane & 1;       // i-half
    const int o    = lane >> 1;      // output capsule

    // butterfly permutation of this lane's 8 slots
    const int perm = ((lane >> 2) & 1) | ((lane >> 2) & 2) | ((lane >> 2) & 4);

    // ---- prologue: scaled quaternion + trans, packed per slot-pair (2p,2p+1) ----
    u64 QW[4], QX[4], QY[4], QZ[4], T1[4], T2[4], T3[4];
    const float4* __restrict__ q4 = (const float4*)quats;
#pragma unroll
    for (int p = 0; p < 4; p++) {
        float qc[2][4], tc[2][3];
#pragma unroll
        for (int s = 0; s < 2; s++) {
            const int pi = o * 16 + h * 8 + ((2 * p + s) ^ perm);
            const float4 q = __ldg(&q4[pi]);
            const float f = rsqrtf(fmaf(q.x, q.x, fmaf(q.y, q.y, fmaf(q.z, q.z, q.w * q.w))) + EPSF)
                            * __ldg(&scale[pi]);
            qc[s][0] = q.x * f; qc[s][1] = q.y * f; qc[s][2] = q.z * f; qc[s][3] = q.w * f;
            tc[s][0] = __ldg(&trans[pi * 3 + 0]);
            tc[s][1] = __ldg(&trans[pi * 3 + 1]);
            tc[s][2] = __ldg(&trans[pi * 3 + 2]);
        }
        QW[p] = pk2(qc[0][0], qc[1][0]);
        QX[p] = pk2(qc[0][1], qc[1][1]);
        QY[p] = pk2(qc[0][2], qc[1][2]);
        QZ[p] = pk2(qc[0][3], qc[1][3]);
        T1[p] = pk2(tc[0][0], tc[1][0]);
        T2[p] = pk2(tc[0][1], tc[1][1]);
        T3[p] = pk2(tc[0][2], tc[1][2]);
    }
    const float bet = __ldg(&beta[o]);
    const float ab  = __ldg(&alpha[o]) + __ldg(&bias[o]);

    const float4* __restrict__ x4   = (const float4*)x;
    float4* __restrict__       out4 = (float4*)out;

#pragma unroll 1
    for (int n = warp; n < NSAMP; n += TOTAL_WARPS) {
        // ---- votes: packed Hamilton product (FFMA2) ----
        u64 VW[4], VX[4], VY[4], VZ[4];
#pragma unroll
        for (int p = 0; p < 4; p++) {
            const float4 X0 = __ldg(&x4[n * 16 + h * 8 + ((2 * p + 0) ^ perm)]);
            const float4 X1 = __ldg(&x4[n * 16 + h * 8 + ((2 * p + 1) ^ perm)]);
            const u64 XX = pk2(X0.x, X1.x);
            const u64 XY = pk2(X0.y, X1.y);
            const u64 XZ = pk2(X0.z, X1.z);
            const u64 XW = pk2(X0.w, X1.w);

            // vw = qw*Xx - (qx*Xy + qy*Xz + qz*Xw)
            u64 u = mul2(QZ[p], XW);
            u = fma2(QY[p], XZ, u);
            u = fma2(QX[p], XY, u);
            VW[p] = fma2(QW[p], XX, neg2(u));
            // vx = qw*Xy + qx*Xx + qy*Xw - qz*Xz + t1
            u = add2(T1[p], neg2(mul2(QZ[p], XZ)));
            u = fma2(QY[p], XW, u);
            u = fma2(QX[p], XX, u);
            VX[p] = fma2(QW[p], XY, u);
            // vy = qw*Xz - qx*Xw + qy*Xx + qz*Xy + t2
            u = add2(T2[p], neg2(mul2(QX[p], XW)));
            u = fma2(QZ[p], XY, u);
            u = fma2(QY[p], XX, u);
            VY[p] = fma2(QW[p], XZ, u);
            // vz = qw*Xw + qx*Xz - qy*Xy + qz*Xx + t3
            u = add2(T3[p], neg2(mul2(QY[p], XY)));
            u = fma2(QX[p], XZ, u);
            u = fma2(QZ[p], XX, u);
            VZ[p] = fma2(QW[p], XW, u);
        }

        // prefetch next sample's x into L1 (16 lanes cover the 256B sample)
        {
            const int nn = n + TOTAL_WARPS;
            if (nn < NSAMP) {
                const char* pa = (const char*)(x4 + nn * 16) + (lane & 15) * 16;
                asm volatile("prefetch.global.L1 [%0];" :: "l"(pa));
            }
        }

        // ---- dynamic routing, 3 iterations (bb kept packed, log2 domain) ----
        u64 bbP[4];
        float s0, s1, s2, s3, v0, v1, v2, v3, n2 = 0.0f;

#pragma unroll
        for (int iter = 0; iter < 3; iter++) {
            if (iter == 0) {
                // uniform coupling c = 1/16: packed tree sums
                float lo, hi;
                u64 a = add2(add2(VW[0], VW[1]), add2(VW[2], VW[3]));
                upk2(a, lo, hi); s0 = (lo + hi) * 0.0625f;
                a = add2(add2(VX[0], VX[1]), add2(VX[2], VX[3]));
                upk2(a, lo, hi); s1 = (lo + hi) * 0.0625f;
                a = add2(add2(VY[0], VY[1]), add2(VY[2], VY[3]));
                upk2(a, lo, hi); s2 = (lo + hi) * 0.0625f;
                a = add2(add2(VZ[0], VZ[1]), add2(VZ[2], VZ[3]));
                upk2(a, lo, hi); s3 = (lo + hi) * 0.0625f;
            } else {
                // softmax over o: bare ex2 (bb is in log2 domain)
                float e[8], r[8];
#pragma unroll
                for (int p = 0; p < 4; p++) {
                    float blo, bhi;
                    upk2(bbP[p], blo, bhi);
                    e[2 * p + 0] = ex2f(blo);
                    e[2 * p + 1] = ex2f(bhi);
                }
#pragma unroll
                for (int m = 0; m < 8; m++) r[m] = e[m];

                // select-free reduce-scatter (slot m <-> logical m^perm)
#pragma unroll
                for (int j = 0; j < 4; j++)
                    r[j] += __shfl_xor_sync(0xffffffffu, r[j + 4], 16);
#pragma unroll
                for (int j = 0; j < 2; j++)
                    r[j] += __shfl_xor_sync(0xffffffffu, r[j + 2], 8);
                r[0] += __shfl_xor_sync(0xffffffffu, r[1], 4);
                r[0] += __shfl_xor_sync(0xffffffffu, r[0], 2);

                float rden[8];
                rden[0] = fastrcp(r[0]);

                // select-free all-gather
                rden[1] = __shfl_xor_sync(0xffffffffu, rden[0], 4);
                rden[2] = __shfl_xor_sync(0xffffffffu, rden[0], 8);
                rden[3] = __shfl_xor_sync(0xffffffffu, rden[1], 8);
                rden[4] = __shfl_xor_sync(0xffffffffu, rden[0], 16);
                rden[5] = __shfl_xor_sync(0xffffffffu, rden[1], 16);
                rden[6] = __shfl_xor_sync(0xffffffffu, rden[2], 16);
                rden[7] = __shfl_xor_sync(0xffffffffu, rden[3], 16);

                u64 CP[4];
#pragma unroll
                for (int p = 0; p < 4; p++)
                    CP[p] = pk2(e[2 * p] * rden[2 * p], e[2 * p + 1] * rden[2 * p + 1]);

                // packed weighted einsum + horizontal add
                float lo, hi;
                u64 a = mul2(CP[0], VW[0]);
                a = fma2(CP[1], VW[1], a); a = fma2(CP[2], VW[2], a); a = fma2(CP[3], VW[3], a);
                upk2(a, lo, hi); s0 = lo + hi;
                a = mul2(CP[0], VX[0]);
                a = fma2(CP[1], VX[1], a); a = fma2(CP[2], VX[2], a); a = fma2(CP[3], VX[3], a);
                upk2(a, lo, hi); s1 = lo + hi;
                a = mul2(CP[0], VY[0]);
                a = fma2(CP[1], VY[1], a); a = fma2(CP[2], VY[2], a); a = fma2(CP[3], VY[3], a);
                upk2(a, lo, hi); s2 = lo + hi;
                a = mul2(CP[0], VZ[0]);
                a = fma2(CP[1], VZ[1], a); a = fma2(CP[2], VZ[2], a); a = fma2(CP[3], VZ[3], a);
                upk2(a, lo, hi); s3 = lo + hi;
            }
            // fold the two i-halves
            s0 += __shfl_xor_sync(0xffffffffu, s0, 1);
            s1 += __shfl_xor_sync(0xffffffffu, s1, 1);
            s2 += __shfl_xor_sync(0xffffffffu, s2, 1);
            s3 += __shfl_xor_sync(0xffffffffu, s3, 1);

            // squash factor (MUFU chain), fac2 pre-scaled by log2(e)
            n2 = fmaf(s0, s0, fmaf(s1, s1, fmaf(s2, s2, s3 * s3)));
            const float fac  = n2 * fastrcp(1.0f + n2) * rsqrtf(n2 + EPSF);
            const float fac2 = fac * LOG2E;

            // packed b-update: bb (+)= fac2 * (s . vote)
            if (iter < 2) {
                const u64 S0 = pk2(s0, s0), S1 = pk2(s1, s1);
                const u64 S2 = pk2(s2, s2), S3 = pk2(s3, s3);
                const u64 FC = pk2(fac2, fac2);
#pragma unroll
                for (int p = 0; p < 4; p++) {
                    u64 d = mul2(S3, VZ[p]);
                    d = fma2(S2, VY[p], d);
                    d = fma2(S1, VX[p], d);
                    d = fma2(S0, VW[p], d);
                    bbP[p] = (iter == 0) ? mul2(FC, d) : fma2(FC, d, bbP[p]);
                }
            }

            v0 = s0 * fac; v1 = s1 * fac; v2 = s2 * fac; v3 = s3 * fac;
        }

        // ---- activation + store (even lanes: one coalesced float4 per (n,o)) ----
        const float norm_s = sqrtf(n2 + EPSF);
        const float z = fmaf(bet, norm_s, ab);
        const float a = fastrcp(1.0f + __expf(-z));

        if (h == 0) {
            out4[n * 16 + o] = make_float4(v0 * a, v1 * a, v2 * a, v3 * a);
        }
    }
}

extern "C" void kernel_launch(void* const* d_in, const int* in_sizes, int n_in,
                              void* d_out, int out_size)
{
    const float* x     = (const float*)d_in[0];
    const float* quats = (const float*)d_in[1];
    const float* scale = (const float*)d_in[2];
    const float* trans = (const float*)d_in[3];
    const float* bias  = (const float*)d_in[4];
    const float* beta  = (const float*)d_in[5];
    const float* alpha = (const float*)d_in[6];

    caps_quat_kernel<<<NBLOCKS, BLOCK_THREADS>>>(x, quats, scale, trans, bias, beta, alpha,
                                                 (float*)d_out);
}

// round 16
// speedup vs baseline: 1.1058x; 1.1058x over previous
#include <cuda_runtime.h>

#define NSAMP 65536
#define EPSF 1e-8f
#define LOG2E 1.44269504f
#define BLOCK_THREADS 128
#define NBLOCKS 592                    // 4 CTAs/SM x 148 SMs: single resident wave
#define TOTAL_WARPS (NBLOCKS * (BLOCK_THREADS / 32))
#define FULLM 0xffffffffu

// Warp-per-sample, register-resident, single-wave persistent kernel.
// Lane l -> (o = l>>1, i-half h = l&1); butterfly slot order: slot m holds
// logical i = h*8 + (m^perm), perm bits from lane bits 2,3,4 (xor 4/8/16).
// Softmax den: RADIX-8 + RADIX-4 reduce-scatter (2 dependent stages instead
// of 4) and single-stage radix-8 all-gather (rden[m] = shfl(rden0, 4m)) --
// den-chain depth ~100cyc vs ~200. b kept in log2 domain (bare ex2.approx).

__device__ __forceinline__ float fastrcp(float d) {
    float r; asm("rcp.approx.f32 %0, %1;" : "=f"(r) : "f"(d)); return r;
}
__device__ __forceinline__ float ex2f(float v) {
    float r; asm("ex2.approx.f32 %0, %1;" : "=f"(r) : "f"(v)); return r;
}

__global__ void __launch_bounds__(BLOCK_THREADS, 4)
caps_quat_kernel(const float* __restrict__ x,
                 const float* __restrict__ quats,
                 const float* __restrict__ scale,
                 const float* __restrict__ trans,
                 const float* __restrict__ bias,
                 const float* __restrict__ beta,
                 const float* __restrict__ alpha,
                 float* __restrict__ out)
{
    const int lane = threadIdx.x & 31;
    const int warp = blockIdx.x * (BLOCK_THREADS / 32) + (threadIdx.x >> 5);
    const int h    = lane & 1;       // i-half
    const int o    = lane >> 1;      // output capsule

    // butterfly permutation of this lane's 8 slots (bits from lane 4/8/16)
    const int perm = ((lane >> 2) & 1) | ((lane >> 2) & 2) | ((lane >> 2) & 4);

    // ---- one-time prologue: scaled quaternion + trans, loaded in slot order ----
    float qw[8], qx[8], qy[8], qz[8], t1[8], t2[8], t3[8];
    const float4* __restrict__ q4 = (const float4*)quats;
#pragma unroll
    for (int m = 0; m < 8; m++) {
        const int pi = o * 16 + h * 8 + (m ^ perm);
        const float4 q = __ldg(&q4[pi]);
        const float f = rsqrtf(fmaf(q.x, q.x, fmaf(q.y, q.y, fmaf(q.z, q.z, q.w * q.w))) + EPSF)
                        * __ldg(&scale[pi]);
        qw[m] = q.x * f; qx[m] = q.y * f; qy[m] = q.z * f; qz[m] = q.w * f;
        t1[m] = __ldg(&trans[pi * 3 + 0]);
        t2[m] = __ldg(&trans[pi * 3 + 1]);
        t3[m] = __ldg(&trans[pi * 3 + 2]);
    }
    const float bet = __ldg(&beta[o]);
    const float ab  = __ldg(&alpha[o]) + __ldg(&bias[o]);

    const float4* __restrict__ x4   = (const float4*)x;
    float4* __restrict__       out4 = (float4*)out;

#pragma unroll 1
    for (int n = warp; n < NSAMP; n += TOTAL_WARPS) {
        // ---- votes: Hamilton product (x loaded in slot order) ----
        float vw[8], vx[8], vy[8], vz[8];
#pragma unroll
        for (int m = 0; m < 8; m++) {
            const float4 X = __ldg(&x4[n * 16 + h * 8 + (m ^ perm)]);
            vw[m] = fmaf(qw[m], X.x, fmaf(-qx[m], X.y, fmaf(-qy[m], X.z, -qz[m] * X.w)));
            vx[m] = fmaf(qw[m], X.y, fmaf( qx[m], X.x, fmaf( qy[m], X.w, fmaf(-qz[m], X.z, t1[m]))));
            vy[m] = fmaf(qw[m], X.z, fmaf(-qx[m], X.w, fmaf( qy[m], X.x, fmaf( qz[m], X.y, t2[m]))));
            vz[m] = fmaf(qw[m], X.w, fmaf( qx[m], X.z, fmaf(-qy[m], X.y, fmaf( qz[m], X.x, t3[m]))));
        }

        // prefetch next sample's x into L1 (16 lanes cover the 256B sample)
        {
            const int nn = n + TOTAL_WARPS;
            if (nn < NSAMP) {
                const char* pa = (const char*)(x4 + nn * 16) + (lane & 15) * 16;
                asm volatile("prefetch.global.L1 [%0];" :: "l"(pa));
            }
        }

        // ---- dynamic routing, 3 iterations (bb in log2 domain) ----
        float bb[8];
        float s0, s1, s2, s3, v0, v1, v2, v3, n2 = 0.0f, rsqLast = 0.0f;

#pragma unroll
        for (int iter = 0; iter < 3; iter++) {
            if (iter == 0) {
                // b == 0 -> uniform coupling c = 1/16 (tree-shaped sums)
                s0 = (((vw[0] + vw[1]) + (vw[2] + vw[3])) + ((vw[4] + vw[5]) + (vw[6] + vw[7]))) * 0.0625f;
                s1 = (((vx[0] + vx[1]) + (vx[2] + vx[3])) + ((vx[4] + vx[5]) + (vx[6] + vx[7]))) * 0.0625f;
                s2 = (((vy[0] + vy[1]) + (vy[2] + vy[3])) + ((vy[4] + vy[5]) + (vy[6] + vy[7]))) * 0.0625f;
                s3 = (((vz[0] + vz[1]) + (vz[2] + vz[3])) + ((vz[4] + vz[5]) + (vz[6] + vz[7]))) * 0.0625f;
            } else {
                // softmax over o: bb is log2-domain -> bare ex2
                float e[8];
#pragma unroll
                for (int m = 0; m < 8; m++) e[m] = ex2f(bb[m]);

                // --- radix reduce-scatter, 2 dependent stages ---
                // stage 1 (radix-8 over lane-xors 8,16,24): 6 independent shfls
                const float r1_0 = ((e[0] + __shfl_xor_sync(FULLM, e[2], 8))
                                  + (__shfl_xor_sync(FULLM, e[4], 16)
                                  +  __shfl_xor_sync(FULLM, e[6], 24)));
                const float r1_1 = ((e[1] + __shfl_xor_sync(FULLM, e[3], 8))
                                  + (__shfl_xor_sync(FULLM, e[5], 16)
                                  +  __shfl_xor_sync(FULLM, e[7], 24)));
                // stage 2 (radix-4 over lane-xors 2,4,6): 3 independent shfls
                const float den = ((r1_0 + __shfl_xor_sync(FULLM, r1_0, 2))
                                 + (__shfl_xor_sync(FULLM, r1_1, 4)
                                 +  __shfl_xor_sync(FULLM, r1_1, 6)));

                float rden[8];
                rden[0] = fastrcp(den);

                // --- single-stage all-gather: den for logical m^perm lives
                //     at lane L ^ (4*m); 7 independent shfls, depth 1 ---
                rden[1] = __shfl_xor_sync(FULLM, rden[0], 4);
                rden[2] = __shfl_xor_sync(FULLM, rden[0], 8);
                rden[3] = __shfl_xor_sync(FULLM, rden[0], 12);
                rden[4] = __shfl_xor_sync(FULLM, rden[0], 16);
                rden[5] = __shfl_xor_sync(FULLM, rden[0], 20);
                rden[6] = __shfl_xor_sync(FULLM, rden[0], 24);
                rden[7] = __shfl_xor_sync(FULLM, rden[0], 28);

                float c[8];
#pragma unroll
                for (int m = 0; m < 8; m++) c[m] = e[m] * rden[m];

                // weighted einsum, tree-shaped
                {
                    const float a0 = fmaf(c[1], vw[1], c[0] * vw[0]);
                    const float a1 = fmaf(c[3], vw[3], c[2] * vw[2]);
                    const float a2 = fmaf(c[5], vw[5], c[4] * vw[4]);
                    const float a3 = fmaf(c[7], vw[7], c[6] * vw[6]);
                    s0 = (a0 + a1) + (a2 + a3);
                }
                {
                    const float a0 = fmaf(c[1], vx[1], c[0] * vx[0]);
                    const float a1 = fmaf(c[3], vx[3], c[2] * vx[2]);
                    const float a2 = fmaf(c[5], vx[5], c[4] * vx[4]);
                    const float a3 = fmaf(c[7], vx[7], c[6] * vx[6]);
                    s1 = (a0 + a1) + (a2 + a3);
                }
                {
                    const float a0 = fmaf(c[1], vy[1], c[0] * vy[0]);
                    const float a1 = fmaf(c[3], vy[3], c[2] * vy[2]);
                    const float a2 = fmaf(c[5], vy[5], c[4] * vy[4]);
                    const float a3 = fmaf(c[7], vy[7], c[6] * vy[6]);
                    s2 = (a0 + a1) + (a2 + a3);
                }
                {
                    const float a0 = fmaf(c[1], vz[1], c[0] * vz[0]);
                    const float a1 = fmaf(c[3], vz[3], c[2] * vz[2]);
                    const float a2 = fmaf(c[5], vz[5], c[4] * vz[4]);
                    const float a3 = fmaf(c[7], vz[7], c[6] * vz[6]);
                    s3 = (a0 + a1) + (a2 + a3);
                }
            }
            // fold the two i-halves
            s0 += __shfl_xor_sync(FULLM, s0, 1);
            s1 += __shfl_xor_sync(FULLM, s1, 1);
            s2 += __shfl_xor_sync(FULLM, s2, 1);
            s3 += __shfl_xor_sync(FULLM, s3, 1);

            // squash factor (MUFU chain), overlapped with b-update dot products
            n2 = fmaf(s0, s0, fmaf(s1, s1, fmaf(s2, s2, s3 * s3)));
            const float rsq  = rsqrtf(n2 + EPSF);
            const float fac  = n2 * fastrcp(1.0f + n2) * rsq;
            const float fac2 = fac * LOG2E;          // b stays in log2 domain
            rsqLast = rsq;

            if (iter == 0) {
#pragma unroll
                for (int m = 0; m < 8; m++) {
                    const float d = fmaf(s0, vw[m], fmaf(s1, vx[m], fmaf(s2, vy[m], s3 * vz[m])));
                    bb[m] = fac2 * d;
                }
            } else if (iter == 1) {
#pragma unroll
                for (int m = 0; m < 8; m++) {
                    const float d = fmaf(s0, vw[m], fmaf(s1, vx[m], fmaf(s2, vy[m], s3 * vz[m])));
                    bb[m] = fmaf(fac2, d, bb[m]);
                }
            }

            v0 = s0 * fac; v1 = s1 * fac; v2 = s2 * fac; v3 = s3 * fac;
        }

        // ---- activation + store (even lanes: one coalesced float4 per (n,o)) ----
        const float norm_s = (n2 + EPSF) * rsqLast;          // == sqrt(n2+eps)
        const float z = fmaf(bet, norm_s, ab);
        const float a = fastrcp(1.0f + ex2f(-z * LOG2E));    // sigmoid

        if (h == 0) {
            out4[n * 16 + o] = make_float4(v0 * a, v1 * a, v2 * a, v3 * a);
        }
    }
}

extern "C" void kernel_launch(void* const* d_in, const int* in_sizes, int n_in,
                              void* d_out, int out_size)
{
    const float* x     = (const float*)d_in[0];
    const float* quats = (const float*)d_in[1];
    const float* scale = (const float*)d_in[2];
    const float* trans = (const float*)d_in[3];
    const float* bias  = (const float*)d_in[4];
    const float* beta  = (const float*)d_in[5];
    const float* alpha = (const float*)d_in[6];

    caps_quat_kernel<<<NBLOCKS, BLOCK_THREADS>>>(x, quats, scale, trans, bias, beta, alpha,
                                                 (float*)d_out);
}